// round 13
// baseline (speedup 1.0000x reference)
#include <cuda_runtime.h>
#include <cstdint>

#define D        768
#define DV       (D / 4)     // 192 float4 per row
#define E        8
#define RB       4           // rows per warp-batch
#define NJ       6           // k-iterations (32 float4 per iter)
#define WRP      8           // warps per CTA (4 TMA + 4 LDG)
#define TWRP     4           // TMA warps per CTA
#define THREADS  256
#define SLOT     (RB * DV)           // 768 float4 = 12 KB per buffer
#define SLOT_BYTES (RB * D * 4)      // 12288

typedef unsigned long long ull;

__device__ __forceinline__ void ffma2(ull& d, ull a, ull b) {
    asm("fma.rn.f32x2 %0, %1, %2, %0;" : "+l"(d) : "l"(a), "l"(b));
}
__device__ __forceinline__ uint32_t s2u(const void* p) {
    uint32_t a;
    asm("{ .reg .u64 t; cvta.to.shared.u64 t, %1; cvt.u32.u64 %0, t; }"
        : "=r"(a) : "l"(p));
    return a;
}
__device__ __forceinline__ void mbar_init(uint32_t m, uint32_t cnt) {
    asm volatile("mbarrier.init.shared.b64 [%0], %1;" :: "r"(m), "r"(cnt) : "memory");
}
__device__ __forceinline__ void mbar_expect_tx(uint32_t m, uint32_t bytes) {
    asm volatile("mbarrier.arrive.expect_tx.shared.b64 _, [%0], %1;"
                 :: "r"(m), "r"(bytes) : "memory");
}
__device__ __forceinline__ void mbar_wait(uint32_t m, uint32_t phase) {
    asm volatile(
        "{\n\t"
        ".reg .pred P1;\n\t"
        "LAB_WAIT_%=:\n\t"
        "mbarrier.try_wait.parity.acquire.cta.shared::cta.b64 P1, [%0], %1, 0x989680;\n\t"
        "@P1 bra LAB_DONE_%=;\n\t"
        "bra LAB_WAIT_%=;\n\t"
        "LAB_DONE_%=:\n\t"
        "}"
        :: "r"(m), "r"(phase) : "memory");
}
__device__ __forceinline__ void bulk_g2s(uint32_t dst, const void* src,
                                         uint32_t bytes, uint32_t m) {
    asm volatile(
        "cp.async.bulk.shared::cta.global.mbarrier::complete_tx::bytes [%0], [%1], %2, [%3];"
        :: "r"(dst), "l"(src), "r"(bytes), "r"(m) : "memory");
}

// shared epilogue: v[32] transposed-reduced -> logits + top2 softmax, then store
__device__ __forceinline__ void epilogue(float v[RB * E], int lane, int row0,
                                         const float* b_sh, float* out, int B) {
    float* out_idx = out;
    float* out_wt  = out + (size_t)2 * B;
    float* out_lg  = out + (size_t)4 * B;

    // Butterfly transpose-reduction: lane l ends with full k-sum of value l
    #pragma unroll
    for (int off = 16; off >= 1; off >>= 1) {
        const bool up = (lane & off) != 0;
        #pragma unroll
        for (int q = 0; q < off; q++) {
            float send = up ? v[q] : v[q + off];
            float recv = __shfl_xor_sync(0xffffffffu, send, off);
            v[q] = (up ? v[q + off] : v[q]) + recv;
        }
    }

    const int e   = lane & 7;
    const int row = row0 + (lane >> 3);
    const float logit = v[0] + b_sh[e];

    out_lg[(size_t)row * E + e] = logit;

    float lv[8];
    #pragma unroll
    for (int k = 0; k < 8; k++)
        lv[k] = __shfl_sync(0xffffffffu, logit, (lane & 24) | k);

    if (e == 0) {
        int i1 = 0; float v1 = lv[0];
        #pragma unroll
        for (int k = 1; k < 8; k++)
            if (lv[k] > v1) { v1 = lv[k]; i1 = k; }
        int i2 = (i1 == 0) ? 1 : 0; float v2 = lv[i2];
        #pragma unroll
        for (int k = 0; k < 8; k++)
            if (k != i1 && lv[k] > v2) { v2 = lv[k]; i2 = k; }

        const float tt = __expf(v2 - v1);
        const float w1 = 1.0f / (1.0f + tt);
        const float w2 = tt * w1;

        out_idx[(size_t)row * 2]     = (float)i1;
        out_idx[(size_t)row * 2 + 1] = (float)i2;
        out_wt [(size_t)row * 2]     = w1;
        out_wt [(size_t)row * 2 + 1] = w2;
    }
}

__global__ __launch_bounds__(THREADS, 1)
void router_kernel(const float* __restrict__ h,
                   const float* __restrict__ gw,
                   const float* __restrict__ gb,
                   float* __restrict__ out, int B) {
    extern __shared__ float4 smem[];
    float4* ws   = smem;                        // 24 KB row-major w copy
    float4* xbuf = smem + 8 * DV;               // TWRP*2*SLOT = 96 KB TMA staging
    float*  b_sh = (float*)(xbuf + TWRP * 2 * SLOT);
    uint64_t* mbars = (uint64_t*)(b_sh + 8);    // 8 mbarriers (TMA warp, buf)

    const float4* gw4 = reinterpret_cast<const float4*>(gw);
    for (int i = threadIdx.x; i < 8 * DV; i += THREADS)
        ws[i] = gw4[i];
    if (threadIdx.x < E) b_sh[threadIdx.x] = gb[threadIdx.x];

    if (threadIdx.x == 0) {
        for (int i = 0; i < TWRP * 2; i++)
            mbar_init(s2u(mbars) + 8u * i, 1);
        asm volatile("fence.proxy.async.shared::cta;" ::: "memory");
    }
    __syncthreads();   // only CTA-wide sync

    const ulonglong2* wsu = reinterpret_cast<const ulonglong2*>(ws);

    const int lane = threadIdx.x & 31;
    const int warp = threadIdx.x >> 5;
    const int nbatch = B / RB;                  // 8192
    const int SPLIT  = (nbatch * 9) >> 4;       // 9/16 to TMA (rate 17:14)

    const float4* h4 = reinterpret_cast<const float4*>(h);

    if (warp < TWRP) {
        // ───────────── TMA path: batches [0, SPLIT) ─────────────
        const int gwarp  = blockIdx.x * TWRP + warp;
        const int nwarps = gridDim.x * TWRP;    // 592

        float4* xw = xbuf + warp * (2 * SLOT);
        const uint32_t xs0 = s2u(xw);
        const uint32_t xs1 = xs0 + SLOT_BYTES;
        const uint32_t mb0 = s2u(mbars) + (uint32_t)warp * 16u;
        const uint32_t mb1 = mb0 + 8u;

        if (lane == 0) {
            if (gwarp < SPLIT) {
                mbar_expect_tx(mb0, SLOT_BYTES);
                bulk_g2s(xs0, h + (size_t)gwarp * RB * D, SLOT_BYTES, mb0);
            }
            if (gwarp + nwarps < SPLIT) {
                mbar_expect_tx(mb1, SLOT_BYTES);
                bulk_g2s(xs1, h + (size_t)(gwarp + nwarps) * RB * D, SLOT_BYTES, mb1);
            }
        }

        int i = 0;
        for (int batch = gwarp; batch < SPLIT; batch += nwarps, i++) {
            const int buf = i & 1;
            mbar_wait(buf ? mb1 : mb0, (i >> 1) & 1);

            const float4* xt = xw + buf * SLOT;

            ull acc2[RB][E];
            #pragma unroll
            for (int r = 0; r < RB; r++)
                #pragma unroll
                for (int e = 0; e < E; e++) acc2[r][e] = 0ull;

            #pragma unroll
            for (int j = 0; j < NJ; j++) {
                const int k4 = j * 32 + lane;
                ulonglong2 xu[RB];
                #pragma unroll
                for (int r = 0; r < RB; r++)
                    xu[r] = *reinterpret_cast<const ulonglong2*>(&xt[r * DV + k4]);
                #pragma unroll
                for (int e = 0; e < E; e++) {
                    const ulonglong2 we = wsu[e * DV + k4];
                    #pragma unroll
                    for (int r = 0; r < RB; r++) {
                        ffma2(acc2[r][e], we.x, xu[r].x);
                        ffma2(acc2[r][e], we.y, xu[r].y);
                    }
                }
            }

            __syncwarp();
            if (lane == 0) {
                const int nb = batch + 2 * nwarps;
                if (nb < SPLIT) {
                    const uint32_t mbn = buf ? mb1 : mb0;
                    mbar_expect_tx(mbn, SLOT_BYTES);
                    bulk_g2s(buf ? xs1 : xs0, h + (size_t)nb * RB * D, SLOT_BYTES, mbn);
                }
            }

            float v[RB * E];
            #pragma unroll
            for (int r = 0; r < RB; r++)
                #pragma unroll
                for (int e = 0; e < E; e++) {
                    uint32_t lo, hi;
                    asm("mov.b64 {%0, %1}, %2;" : "=r"(lo), "=r"(hi) : "l"(acc2[r][e]));
                    v[r * E + e] = __uint_as_float(lo) + __uint_as_float(hi);
                }

            epilogue(v, lane, batch * RB, b_sh, out, B);
        }
    } else {
        // ───────────── LDG path: batches [SPLIT, nbatch) ─────────────
        const int gwarp  = blockIdx.x * (WRP - TWRP) + (warp - TWRP);
        const int nwarps = gridDim.x * (WRP - TWRP);   // 592

        #pragma unroll 1
        for (int batch = SPLIT + gwarp; batch < nbatch; batch += nwarps) {
            const int row0 = batch * RB;
            const float4* hb = h4 + (size_t)row0 * DV;

            ull acc2[RB][E];
            #pragma unroll
            for (int r = 0; r < RB; r++)
                #pragma unroll
                for (int e = 0; e < E; e++) acc2[r][e] = 0ull;

            // fully unrolled: up to 24 LDG.128 hoisted for high MLP
            #pragma unroll
            for (int j = 0; j < NJ; j++) {
                const int k4 = j * 32 + lane;
                ulonglong2 xu[RB];
                #pragma unroll
                for (int r = 0; r < RB; r++)
                    xu[r] = *reinterpret_cast<const ulonglong2*>(&hb[r * DV + k4]);
                #pragma unroll
                for (int e = 0; e < E; e++) {
                    const ulonglong2 we = wsu[e * DV + k4];
                    #pragma unroll
                    for (int r = 0; r < RB; r++) {
                        ffma2(acc2[r][e], we.x, xu[r].x);
                        ffma2(acc2[r][e], we.y, xu[r].y);
                    }
                }
            }

            float v[RB * E];
            #pragma unroll
            for (int r = 0; r < RB; r++)
                #pragma unroll
                for (int e = 0; e < E; e++) {
                    uint32_t lo, hi;
                    asm("mov.b64 {%0, %1}, %2;" : "=r"(lo), "=r"(hi) : "l"(acc2[r][e]));
                    v[r * E + e] = __uint_as_float(lo) + __uint_as_float(hi);
                }

            epilogue(v, lane, row0, b_sh, out, B);
        }
    }
}

extern "C" void kernel_launch(void* const* d_in, const int* in_sizes, int n_in,
                              void* d_out, int out_size) {
    const float* h  = (const float*)d_in[0];   // [B, 768]
    const float* gw = (const float*)d_in[1];   // [8, 768]
    const float* gb = (const float*)d_in[2];   // [8]
    float* out = (float*)d_out;

    const int B = in_sizes[0] / D;             // 32768

    // smem: 24KB w + 96KB TMA staging + bias + 8 mbarriers
    const int smem_bytes = (8 * DV + TWRP * 2 * SLOT) * 16 + 64 + 8 * 8;
    cudaFuncSetAttribute(router_kernel,
                         cudaFuncAttributeMaxDynamicSharedMemorySize, smem_bytes);

    // persistent: 1 CTA per SM; 4 TMA-fed warps + 4 LDG-fed warps per SM
    const int blocks = 148;
    router_kernel<<<blocks, THREADS, smem_bytes>>>(h, gw, gb, out, B);
}

// round 14
// speedup vs baseline: 1.6635x; 1.6635x over previous
#include <cuda_runtime.h>
#include <cstdint>

#define D        768
#define DV       (D / 4)     // 192 float4 per row
#define E        8
#define RB       4           // rows per warp-batch
#define NJ       6           // k-iterations (32 float4 per iter)
#define TWRP     4           // TMA warps per CTA
#define LWRP     12          // LDG warps per CTA
#define THREADS  512
#define SLOT     (RB * DV)           // 768 float4 = 12 KB per buffer
#define SLOT_BYTES (RB * D * 4)      // 12288

typedef unsigned long long ull;

__device__ __forceinline__ void ffma2(ull& d, ull a, ull b) {
    asm("fma.rn.f32x2 %0, %1, %2, %0;" : "+l"(d) : "l"(a), "l"(b));
}
__device__ __forceinline__ uint32_t s2u(const void* p) {
    uint32_t a;
    asm("{ .reg .u64 t; cvta.to.shared.u64 t, %1; cvt.u32.u64 %0, t; }"
        : "=r"(a) : "l"(p));
    return a;
}
__device__ __forceinline__ void mbar_init(uint32_t m, uint32_t cnt) {
    asm volatile("mbarrier.init.shared.b64 [%0], %1;" :: "r"(m), "r"(cnt) : "memory");
}
__device__ __forceinline__ void mbar_expect_tx(uint32_t m, uint32_t bytes) {
    asm volatile("mbarrier.arrive.expect_tx.shared.b64 _, [%0], %1;"
                 :: "r"(m), "r"(bytes) : "memory");
}
__device__ __forceinline__ void mbar_wait(uint32_t m, uint32_t phase) {
    asm volatile(
        "{\n\t"
        ".reg .pred P1;\n\t"
        "LAB_WAIT_%=:\n\t"
        "mbarrier.try_wait.parity.acquire.cta.shared::cta.b64 P1, [%0], %1, 0x989680;\n\t"
        "@P1 bra LAB_DONE_%=;\n\t"
        "bra LAB_WAIT_%=;\n\t"
        "LAB_DONE_%=:\n\t"
        "}"
        :: "r"(m), "r"(phase) : "memory");
}
__device__ __forceinline__ void bulk_g2s(uint32_t dst, const void* src,
                                         uint32_t bytes, uint32_t m) {
    asm volatile(
        "cp.async.bulk.shared::cta.global.mbarrier::complete_tx::bytes [%0], [%1], %2, [%3];"
        :: "r"(dst), "l"(src), "r"(bytes), "r"(m) : "memory");
}

// shared epilogue: v[32] -> butterfly reduce -> logits + top2 softmax -> store
__device__ __forceinline__ void epilogue(float v[RB * E], int lane, int row0,
                                         const float* b_sh, float* out, int B) {
    float* out_idx = out;
    float* out_wt  = out + (size_t)2 * B;
    float* out_lg  = out + (size_t)4 * B;

    #pragma unroll
    for (int off = 16; off >= 1; off >>= 1) {
        const bool up = (lane & off) != 0;
        #pragma unroll
        for (int q = 0; q < off; q++) {
            float send = up ? v[q] : v[q + off];
            float recv = __shfl_xor_sync(0xffffffffu, send, off);
            v[q] = (up ? v[q + off] : v[q]) + recv;
        }
    }

    const int e   = lane & 7;
    const int row = row0 + (lane >> 3);
    const float logit = v[0] + b_sh[e];

    out_lg[(size_t)row * E + e] = logit;

    float lv[8];
    #pragma unroll
    for (int k = 0; k < 8; k++)
        lv[k] = __shfl_sync(0xffffffffu, logit, (lane & 24) | k);

    if (e == 0) {
        int i1 = 0; float v1 = lv[0];
        #pragma unroll
        for (int k = 1; k < 8; k++)
            if (lv[k] > v1) { v1 = lv[k]; i1 = k; }
        int i2 = (i1 == 0) ? 1 : 0; float v2 = lv[i2];
        #pragma unroll
        for (int k = 0; k < 8; k++)
            if (k != i1 && lv[k] > v2) { v2 = lv[k]; i2 = k; }

        const float tt = __expf(v2 - v1);
        const float w1 = 1.0f / (1.0f + tt);
        const float w2 = tt * w1;

        out_idx[(size_t)row * 2]     = (float)i1;
        out_idx[(size_t)row * 2 + 1] = (float)i2;
        out_wt [(size_t)row * 2]     = w1;
        out_wt [(size_t)row * 2 + 1] = w2;
    }
}

__global__ __launch_bounds__(THREADS, 1)   // caps regs at 128/thread
void router_kernel(const float* __restrict__ h,
                   const float* __restrict__ gw,
                   const float* __restrict__ gb,
                   float* __restrict__ out, int B) {
    extern __shared__ float4 smem[];
    float4* ws   = smem;                        // 24 KB row-major w copy
    float4* xbuf = smem + 8 * DV;               // TWRP*2*SLOT = 96 KB TMA staging
    float*  b_sh = (float*)(xbuf + TWRP * 2 * SLOT);
    uint64_t* mbars = (uint64_t*)(b_sh + 8);    // 8 mbarriers (TMA warp, buf)

    const float4* gw4 = reinterpret_cast<const float4*>(gw);
    for (int i = threadIdx.x; i < 8 * DV; i += THREADS)
        ws[i] = gw4[i];
    if (threadIdx.x < E) b_sh[threadIdx.x] = gb[threadIdx.x];

    if (threadIdx.x == 0) {
        for (int i = 0; i < TWRP * 2; i++)
            mbar_init(s2u(mbars) + 8u * i, 1);
        asm volatile("fence.proxy.async.shared::cta;" ::: "memory");
    }
    __syncthreads();   // only CTA-wide sync

    const ulonglong2* wsu = reinterpret_cast<const ulonglong2*>(ws);

    const int lane = threadIdx.x & 31;
    const int warp = threadIdx.x >> 5;
    const int nbatch = B / RB;                  // 8192
    const int SPLIT  = (nbatch * 9) >> 4;       // 9/16 -> TMA, 7/16 -> LDG

    const float4* h4 = reinterpret_cast<const float4*>(h);

    if (warp < TWRP) {
        // ───────────── TMA path (R11 pattern): batches [0, SPLIT) ─────────────
        const int gwarp  = blockIdx.x * TWRP + warp;
        const int nwarps = gridDim.x * TWRP;    // 592

        float4* xw = xbuf + warp * (2 * SLOT);
        const uint32_t xs0 = s2u(xw);
        const uint32_t xs1 = xs0 + SLOT_BYTES;
        const uint32_t mb0 = s2u(mbars) + (uint32_t)warp * 16u;
        const uint32_t mb1 = mb0 + 8u;

        if (lane == 0) {
            if (gwarp < SPLIT) {
                mbar_expect_tx(mb0, SLOT_BYTES);
                bulk_g2s(xs0, h + (size_t)gwarp * RB * D, SLOT_BYTES, mb0);
            }
            if (gwarp + nwarps < SPLIT) {
                mbar_expect_tx(mb1, SLOT_BYTES);
                bulk_g2s(xs1, h + (size_t)(gwarp + nwarps) * RB * D, SLOT_BYTES, mb1);
            }
        }

        int i = 0;
        #pragma unroll 1
        for (int batch = gwarp; batch < SPLIT; batch += nwarps, i++) {
            const int buf = i & 1;
            mbar_wait(buf ? mb1 : mb0, (i >> 1) & 1);

            const float4* xt = xw + buf * SLOT;

            ull acc2[RB][E];
            #pragma unroll
            for (int r = 0; r < RB; r++)
                #pragma unroll
                for (int e = 0; e < E; e++) acc2[r][e] = 0ull;

            #pragma unroll
            for (int j = 0; j < NJ; j++) {
                const int k4 = j * 32 + lane;
                ulonglong2 xu[RB];
                #pragma unroll
                for (int r = 0; r < RB; r++)
                    xu[r] = *reinterpret_cast<const ulonglong2*>(&xt[r * DV + k4]);
                #pragma unroll
                for (int e = 0; e < E; e++) {
                    const ulonglong2 we = wsu[e * DV + k4];
                    #pragma unroll
                    for (int r = 0; r < RB; r++) {
                        ffma2(acc2[r][e], we.x, xu[r].x);
                        ffma2(acc2[r][e], we.y, xu[r].y);
                    }
                }
            }

            __syncwarp();
            if (lane == 0) {
                const int nb = batch + 2 * nwarps;
                if (nb < SPLIT) {
                    const uint32_t mbn = buf ? mb1 : mb0;
                    mbar_expect_tx(mbn, SLOT_BYTES);
                    bulk_g2s(buf ? xs1 : xs0, h + (size_t)nb * RB * D, SLOT_BYTES, mbn);
                }
            }

            float v[RB * E];
            #pragma unroll
            for (int r = 0; r < RB; r++)
                #pragma unroll
                for (int e = 0; e < E; e++) {
                    uint32_t lo, hi;
                    asm("mov.b64 {%0, %1}, %2;" : "=r"(lo), "=r"(hi) : "l"(acc2[r][e]));
                    v[r * E + e] = __uint_as_float(lo) + __uint_as_float(hi);
                }

            epilogue(v, lane, batch * RB, b_sh, out, B);
        }
    } else {
        // ───────── LDG path (rolled + rolling prefetch): [SPLIT, nbatch) ─────────
        const int gwarp  = blockIdx.x * LWRP + (warp - TWRP);
        const int nwarps = gridDim.x * LWRP;    // 1776

        #pragma unroll 1
        for (int batch = SPLIT + gwarp; batch < nbatch; batch += nwarps) {
            const int row0 = batch * RB;
            const float4* hb = h4 + (size_t)row0 * DV;

            ull acc2[RB][E];
            #pragma unroll
            for (int r = 0; r < RB; r++)
                #pragma unroll
                for (int e = 0; e < E; e++) acc2[r][e] = 0ull;

            // rolling prefetch: cur j in regs, j+1 in flight (8 LDG.128 MLP)
            ulonglong2 xu[RB];
            #pragma unroll
            for (int r = 0; r < RB; r++)
                xu[r] = *reinterpret_cast<const ulonglong2*>(&hb[r * DV + lane]);

            #pragma unroll 1
            for (int j = 0; j < NJ; j++) {
                const int jn = (j < NJ - 1) ? (j + 1) * 32 + lane : j * 32 + lane;
                ulonglong2 nx[RB];
                #pragma unroll
                for (int r = 0; r < RB; r++)
                    nx[r] = *reinterpret_cast<const ulonglong2*>(&hb[r * DV + jn]);

                const int k4 = j * 32 + lane;
                #pragma unroll
                for (int e = 0; e < E; e++) {
                    const ulonglong2 we = wsu[e * DV + k4];
                    #pragma unroll
                    for (int r = 0; r < RB; r++) {
                        ffma2(acc2[r][e], we.x, xu[r].x);
                        ffma2(acc2[r][e], we.y, xu[r].y);
                    }
                }
                #pragma unroll
                for (int r = 0; r < RB; r++) xu[r] = nx[r];
            }

            float v[RB * E];
            #pragma unroll
            for (int r = 0; r < RB; r++)
                #pragma unroll
                for (int e = 0; e < E; e++) {
                    uint32_t lo, hi;
                    asm("mov.b64 {%0, %1}, %2;" : "=r"(lo), "=r"(hi) : "l"(acc2[r][e]));
                    v[r * E + e] = __uint_as_float(lo) + __uint_as_float(hi);
                }

            epilogue(v, lane, row0, b_sh, out, B);
        }
    }
}

extern "C" void kernel_launch(void* const* d_in, const int* in_sizes, int n_in,
                              void* d_out, int out_size) {
    const float* h  = (const float*)d_in[0];   // [B, 768]
    const float* gw = (const float*)d_in[1];   // [8, 768]
    const float* gb = (const float*)d_in[2];   // [8]
    float* out = (float*)d_out;

    const int B = in_sizes[0] / D;             // 32768

    // smem: 24KB w + 96KB TMA staging + bias + 8 mbarriers
    const int smem_bytes = (8 * DV + TWRP * 2 * SLOT) * 16 + 64 + 8 * 8;
    cudaFuncSetAttribute(router_kernel,
                         cudaFuncAttributeMaxDynamicSharedMemorySize, smem_bytes);

    // persistent: 1 CTA/SM, 512 threads: 4 TMA-fed warps + 12 LDG-fed warps
    const int blocks = 148;
    router_kernel<<<blocks, THREADS, smem_bytes>>>(h, gw, gb, out, B);
}